// round 4
// baseline (speedup 1.0000x reference)
#include <cuda_runtime.h>

// LSTM_584115552367: B=65536 independent LSTMs, D=H=17, T=50, SLB=30.
// R3: 2 elements/thread, f32x2 SIMD along d (no weight duplication).
// Each weight LDS.128 feeds 4 fma2 (2 gates x 2 elements) -> per-element LDS halved vs R2.

#define BSZ   65536
#define TLEN  50
#define DDIM  17
#define SLBC  30
#define NP    9            // padded d-pairs (18/2)
#define TPB   128
#define TOUT  (TLEN - SLBC)

typedef unsigned long long u64;

__device__ __forceinline__ u64 pack2(float lo, float hi) {
    u64 r; asm("mov.b64 %0, {%1, %2};" : "=l"(r) : "f"(lo), "f"(hi)); return r;
}
__device__ __forceinline__ void unpack2(u64 v, float &lo, float &hi) {
    asm("mov.b64 {%0, %1}, %2;" : "=f"(lo), "=f"(hi) : "l"(v));
}
__device__ __forceinline__ void fma2a(u64 &acc, u64 a, u64 b) {
    asm("fma.rn.f32x2 %0, %1, %2, %0;" : "+l"(acc) : "l"(a), "l"(b));
}
__device__ __forceinline__ float hadd2(u64 v) {
    float a, b; unpack2(v, a, b); return a + b;
}

__device__ __forceinline__ float ex2f(float x) {
    float r; asm("ex2.approx.f32 %0, %1;" : "=f"(r) : "f"(x)); return r;
}
__device__ __forceinline__ float rcpf(float x) {
    float r; asm("rcp.approx.f32 %0, %1;" : "=f"(r) : "f"(x)); return r;
}
// sigmoid(x) = 1 / (1 + 2^(-x*log2e)); safe at both extremes (rcp(inf)=0).
__device__ __forceinline__ float sigm(float x) {
    return rcpf(1.0f + ex2f(-1.4426950408889634f * x));
}
// tanh(x) = sign(x)*(1-e)/(1+e), e = 2^(-2|x|*log2e); e<=1, no inf/NaN.
__device__ __forceinline__ float tanhx(float x) {
    float ax = fabsf(x);
    float e  = ex2f(-2.8853900817779268f * ax);
    float r  = (1.0f - e) * rcpf(1.0f + e);
    return copysignf(r, x);
}

__global__ void __launch_bounds__(TPB) lstm_kernel(
    const float* __restrict__ x,     // [B, T, D]
    const float* __restrict__ Wih,   // [4D, D]
    const float* __restrict__ Whh,   // [4D, D]
    const float* __restrict__ bih,   // [4D]
    const float* __restrict__ bhh,   // [4D]
    const float* __restrict__ Wlin,  // [D, D]
    const float* __restrict__ blin,  // [D]
    const float* __restrict__ mih,   // [4D, D]
    const float* __restrict__ mhh,   // [4D, D]
    float* __restrict__ out)         // [B, TOUT, D]
{
    // Gate weights (per hidden unit j, d-pair p):
    //   q=0: ih gates (i,f) d-pairs; q=1: ih (g,o); q=2: hh (i,f); q=3: hh (g,o)
    __shared__ ulonglong2 sWq[DDIM * NP * 4];
    __shared__ ulonglong2 sB[DDIM * 2];     // per j: {(bi,0),(bf,0)}, {(bg,0),(bo,0)}
    __shared__ ulonglong2 sLin2[NP * NP];   // [ccp][p]: {ch 2ccp d-pair, ch 2ccp+1 d-pair}
    __shared__ u64 sBlin[2 * NP];           // (blin[cc], 0), cc padded to 18

    for (int idx = threadIdx.x; idx < DDIM * NP * 4; idx += TPB) {
        int j = idx / 36, r = idx % 36, p = r / 4, q = r % 4;
        const float* W = (q < 2) ? Wih : Whh;
        const float* M = (q < 2) ? mih : mhh;
        int gA = (q & 1) ? (34 + j) : j;
        int gB = (q & 1) ? (51 + j) : (17 + j);
        int d0 = 2 * p, d1 = 2 * p + 1;
        float a0 = W[gA * DDIM + d0] * M[gA * DDIM + d0];
        float a1 = (d1 < DDIM) ? W[gA * DDIM + d1] * M[gA * DDIM + d1] : 0.0f;
        float b0 = W[gB * DDIM + d0] * M[gB * DDIM + d0];
        float b1 = (d1 < DDIM) ? W[gB * DDIM + d1] * M[gB * DDIM + d1] : 0.0f;
        ulonglong2 v; v.x = pack2(a0, a1); v.y = pack2(b0, b1);
        sWq[idx] = v;
    }
    for (int idx = threadIdx.x; idx < NP * NP; idx += TPB) {
        int ccp = idx / NP, p = idx % NP;
        int c0 = 2 * ccp, c1 = 2 * ccp + 1;
        int d0 = 2 * p, d1 = 2 * p + 1;
        float x0 = Wlin[c0 * DDIM + d0];
        float x1 = (d1 < DDIM) ? Wlin[c0 * DDIM + d1] : 0.0f;
        float y0 = (c1 < DDIM) ? Wlin[c1 * DDIM + d0] : 0.0f;
        float y1 = (c1 < DDIM && d1 < DDIM) ? Wlin[c1 * DDIM + d1] : 0.0f;
        ulonglong2 v; v.x = pack2(x0, x1); v.y = pack2(y0, y1);
        sLin2[idx] = v;
    }
    if (threadIdx.x < DDIM) {
        int j = threadIdx.x;
        ulonglong2 v0, v1;
        v0.x = pack2(bih[j]      + bhh[j],      0.0f);
        v0.y = pack2(bih[17 + j] + bhh[17 + j], 0.0f);
        v1.x = pack2(bih[34 + j] + bhh[34 + j], 0.0f);
        v1.y = pack2(bih[51 + j] + bhh[51 + j], 0.0f);
        sB[2 * j] = v0; sB[2 * j + 1] = v1;
    }
    if (threadIdx.x < 2 * NP) {
        int cc = threadIdx.x;
        sBlin[cc] = (cc < DDIM) ? pack2(blin[cc], 0.0f) : 0ull;
    }
    __syncthreads();

    const int gid = blockIdx.x * TPB + threadIdx.x;      // 0..32767
    const long bA = (long)gid * 2;
    const float* __restrict__ xbA = x + bA * (TLEN * DDIM);
    const float* __restrict__ xbB = xbA + (TLEN * DDIM);
    float* __restrict__ obA = out + bA * (TOUT * DDIM);
    float* __restrict__ obB = obA + (TOUT * DDIM);

    u64 xiA[NP], xiB[NP], hA[NP], hB[NP];
    float cA[DDIM], cB[DDIM];
#pragma unroll
    for (int p = 0; p < NP; p++) { xiA[p] = 0ull; xiB[p] = 0ull; hA[p] = 0ull; hB[p] = 0ull; }
#pragma unroll
    for (int j = 0; j < DDIM; j++) { cA[j] = 0.0f; cB[j] = 0.0f; }

#pragma unroll 1
    for (int t = 0; t < TLEN; t++) {
        if (t < SLBC) {
            const float* pA = xbA + t * DDIM;
            const float* pB = xbB + t * DDIM;
#pragma unroll
            for (int p = 0; p < 8; p++) {
                xiA[p] = pack2(pA[2 * p], pA[2 * p + 1]);
                xiB[p] = pack2(pB[2 * p], pB[2 * p + 1]);
            }
            xiA[8] = pack2(pA[16], 0.0f);
            xiB[8] = pack2(pB[16], 0.0f);
        }

        float hnA[DDIM], hnB[DDIM];
#pragma unroll
        for (int j = 0; j < DDIM; j++) {
            ulonglong2 b0 = sB[2 * j], b1 = sB[2 * j + 1];
            u64 aiA = b0.x, afA = b0.y, agA = b1.x, aoA = b1.y;
            u64 aiB = b0.x, afB = b0.y, agB = b1.x, aoB = b1.y;
#pragma unroll
            for (int p = 0; p < NP; p++) {
                ulonglong2 w0 = sWq[(j * NP + p) * 4 + 0];
                ulonglong2 w1 = sWq[(j * NP + p) * 4 + 1];
                ulonglong2 w2 = sWq[(j * NP + p) * 4 + 2];
                ulonglong2 w3 = sWq[(j * NP + p) * 4 + 3];
                fma2a(aiA, xiA[p], w0.x); fma2a(afA, xiA[p], w0.y);
                fma2a(agA, xiA[p], w1.x); fma2a(aoA, xiA[p], w1.y);
                fma2a(aiA, hA[p],  w2.x); fma2a(afA, hA[p],  w2.y);
                fma2a(agA, hA[p],  w3.x); fma2a(aoA, hA[p],  w3.y);
                fma2a(aiB, xiB[p], w0.x); fma2a(afB, xiB[p], w0.y);
                fma2a(agB, xiB[p], w1.x); fma2a(aoB, xiB[p], w1.y);
                fma2a(aiB, hB[p],  w2.x); fma2a(afB, hB[p],  w2.y);
                fma2a(agB, hB[p],  w3.x); fma2a(aoB, hB[p],  w3.y);
            }
            {
                float gi = hadd2(aiA), gf = hadd2(afA), gg = hadd2(agA), go = hadd2(aoA);
                float si = sigm(gi), sf = sigm(gf), tg = tanhx(gg), so = sigm(go);
                float cn = fmaf(sf, cA[j], si * tg);
                cA[j]  = cn;
                hnA[j] = so * tanhx(cn);
            }
            {
                float gi = hadd2(aiB), gf = hadd2(afB), gg = hadd2(agB), go = hadd2(aoB);
                float si = sigm(gi), sf = sigm(gf), tg = tanhx(gg), so = sigm(go);
                float cn = fmaf(sf, cB[j], si * tg);
                cB[j]  = cn;
                hnB[j] = so * tanhx(cn);
            }
        }
#pragma unroll
        for (int p = 0; p < 8; p++) {
            hA[p] = pack2(hnA[2 * p], hnA[2 * p + 1]);
            hB[p] = pack2(hnB[2 * p], hnB[2 * p + 1]);
        }
        hA[8] = pack2(hnA[16], 0.0f);
        hB[8] = pack2(hnB[16], 0.0f);

        if (t >= SLBC - 1) {
            float oA[2 * NP], oB[2 * NP];
#pragma unroll
            for (int ccp = 0; ccp < NP; ccp++) {
                u64 a0A = sBlin[2 * ccp], a1A = sBlin[2 * ccp + 1];
                u64 a0B = a0A, a1B = a1A;
#pragma unroll
                for (int p = 0; p < NP; p++) {
                    ulonglong2 w = sLin2[ccp * NP + p];
                    fma2a(a0A, hA[p], w.x); fma2a(a1A, hA[p], w.y);
                    fma2a(a0B, hB[p], w.x); fma2a(a1B, hB[p], w.y);
                }
                oA[2 * ccp] = hadd2(a0A); oA[2 * ccp + 1] = hadd2(a1A);
                oB[2 * ccp] = hadd2(a0B); oB[2 * ccp + 1] = hadd2(a1B);
            }
            if (t >= SLBC) {
                int tp = t - SLBC;
#pragma unroll
                for (int cc = 0; cc < DDIM; cc++) {
                    obA[tp * DDIM + cc] = oA[cc];
                    obB[tp * DDIM + cc] = oB[cc];
                }
            }
            // Feedback input for next step.
#pragma unroll
            for (int p = 0; p < 8; p++) {
                xiA[p] = pack2(oA[2 * p], oA[2 * p + 1]);
                xiB[p] = pack2(oB[2 * p], oB[2 * p + 1]);
            }
            xiA[8] = pack2(oA[16], 0.0f);
            xiB[8] = pack2(oB[16], 0.0f);
        }
    }
}

extern "C" void kernel_launch(void* const* d_in, const int* in_sizes, int n_in,
                              void* d_out, int out_size) {
    const float* x    = (const float*)d_in[0];
    const float* Wih  = (const float*)d_in[1];
    const float* Whh  = (const float*)d_in[2];
    const float* bih  = (const float*)d_in[3];
    const float* bhh  = (const float*)d_in[4];
    const float* Wlin = (const float*)d_in[5];
    const float* blin = (const float*)d_in[6];
    const float* mih  = (const float*)d_in[7];
    const float* mhh  = (const float*)d_in[8];
    float* out = (float*)d_out;

    dim3 grid(BSZ / (2 * TPB));   // 256 CTAs of 128 threads
    dim3 block(TPB);
    lstm_kernel<<<grid, block>>>(x, Wih, Whh, bih, bhh, Wlin, blin, mih, mhh, out);
}

// round 6
// speedup vs baseline: 1.1701x; 1.1701x over previous
#include <cuda_runtime.h>

// LSTM_584115552367: B=65536 independent LSTMs, D=H=17, T=50, SLB=30.
// R5: R4 (j-pair interleave: 8 acc chains, 8 LDS.128 batched per p-iter)
//     with the x load fixed: row stride is 68B (not 8B-aligned) -> scalar
//     float loads + pack2, as in the proven R2.

#define BSZ   65536
#define TLEN  50
#define DDIM  17
#define SLBC  30
#define NP    9            // padded d-pairs (18/2)
#define TPB   64
#define TOUT  (TLEN - SLBC)

typedef unsigned long long u64;

__device__ __forceinline__ u64 pack2(float lo, float hi) {
    u64 r; asm("mov.b64 %0, {%1, %2};" : "=l"(r) : "f"(lo), "f"(hi)); return r;
}
__device__ __forceinline__ void unpack2(u64 v, float &lo, float &hi) {
    asm("mov.b64 {%0, %1}, %2;" : "=f"(lo), "=f"(hi) : "l"(v));
}
__device__ __forceinline__ void fma2a(u64 &acc, u64 a, u64 b) {
    asm("fma.rn.f32x2 %0, %1, %2, %0;" : "+l"(acc) : "l"(a), "l"(b));
}
__device__ __forceinline__ float hadd2(u64 v) {
    float a, b; unpack2(v, a, b); return a + b;
}

__device__ __forceinline__ float ex2f(float x) {
    float r; asm("ex2.approx.f32 %0, %1;" : "=f"(r) : "f"(x)); return r;
}
__device__ __forceinline__ float rcpf(float x) {
    float r; asm("rcp.approx.f32 %0, %1;" : "=f"(r) : "f"(x)); return r;
}
// sigmoid(x) = 1 / (1 + 2^(-x*log2e)); safe at both extremes (rcp(inf)=0).
__device__ __forceinline__ float sigm(float x) {
    return rcpf(1.0f + ex2f(-1.4426950408889634f * x));
}
// tanh(x) = sign(x)*(1-e)/(1+e), e = 2^(-2|x|*log2e); e<=1, no inf/NaN.
__device__ __forceinline__ float tanhx(float x) {
    float ax = fabsf(x);
    float e  = ex2f(-2.8853900817779268f * ax);
    float r  = (1.0f - e) * rcpf(1.0f + e);
    return copysignf(r, x);
}

__global__ void __launch_bounds__(TPB, 7) lstm_kernel(
    const float* __restrict__ x,     // [B, T, D]
    const float* __restrict__ Wih,   // [4D, D]
    const float* __restrict__ Whh,   // [4D, D]
    const float* __restrict__ bih,   // [4D]
    const float* __restrict__ bhh,   // [4D]
    const float* __restrict__ Wlin,  // [D, D]
    const float* __restrict__ blin,  // [D]
    const float* __restrict__ mih,   // [4D, D]
    const float* __restrict__ mhh,   // [4D, D]
    float* __restrict__ out)         // [B, TOUT, D]
{
    // Gate weights (per hidden unit j, d-pair p):
    //   q=0: ih gates (i,f) d-pairs; q=1: ih (g,o); q=2: hh (i,f); q=3: hh (g,o)
    __shared__ ulonglong2 sWq[DDIM * NP * 4];
    __shared__ ulonglong2 sB[DDIM * 2];     // per j: {(bi,0),(bf,0)}, {(bg,0),(bo,0)}
    __shared__ ulonglong2 sLin2[NP * NP];   // [ccp][p]: {ch 2ccp d-pair, ch 2ccp+1 d-pair}
    __shared__ u64 sBlin[2 * NP];           // (blin[cc], 0), padded to 18

    for (int idx = threadIdx.x; idx < DDIM * NP * 4; idx += TPB) {
        int j = idx / 36, r = idx % 36, p = r / 4, q = r % 4;
        const float* W = (q < 2) ? Wih : Whh;
        const float* M = (q < 2) ? mih : mhh;
        int gA = (q & 1) ? (34 + j) : j;
        int gB = (q & 1) ? (51 + j) : (17 + j);
        int d0 = 2 * p, d1 = 2 * p + 1;
        float a0 = W[gA * DDIM + d0] * M[gA * DDIM + d0];
        float a1 = (d1 < DDIM) ? W[gA * DDIM + d1] * M[gA * DDIM + d1] : 0.0f;
        float b0 = W[gB * DDIM + d0] * M[gB * DDIM + d0];
        float b1 = (d1 < DDIM) ? W[gB * DDIM + d1] * M[gB * DDIM + d1] : 0.0f;
        ulonglong2 v; v.x = pack2(a0, a1); v.y = pack2(b0, b1);
        sWq[idx] = v;
    }
    for (int idx = threadIdx.x; idx < NP * NP; idx += TPB) {
        int ccp = idx / NP, p = idx % NP;
        int c0 = 2 * ccp, c1 = 2 * ccp + 1;
        int d0 = 2 * p, d1 = 2 * p + 1;
        float x0 = Wlin[c0 * DDIM + d0];
        float x1 = (d1 < DDIM) ? Wlin[c0 * DDIM + d1] : 0.0f;
        float y0 = (c1 < DDIM) ? Wlin[c1 * DDIM + d0] : 0.0f;
        float y1 = (c1 < DDIM && d1 < DDIM) ? Wlin[c1 * DDIM + d1] : 0.0f;
        ulonglong2 v; v.x = pack2(x0, x1); v.y = pack2(y0, y1);
        sLin2[idx] = v;
    }
    if (threadIdx.x < DDIM) {
        int j = threadIdx.x;
        ulonglong2 v0, v1;
        v0.x = pack2(bih[j]      + bhh[j],      0.0f);
        v0.y = pack2(bih[17 + j] + bhh[17 + j], 0.0f);
        v1.x = pack2(bih[34 + j] + bhh[34 + j], 0.0f);
        v1.y = pack2(bih[51 + j] + bhh[51 + j], 0.0f);
        sB[2 * j] = v0; sB[2 * j + 1] = v1;
    }
    if (threadIdx.x < 2 * NP) {
        int cc = threadIdx.x;
        sBlin[cc] = (cc < DDIM) ? pack2(blin[cc], 0.0f) : 0ull;
    }
    __syncthreads();

    const int bi = blockIdx.x * TPB + threadIdx.x;   // element index
    const float* __restrict__ xb = x + (long)bi * (TLEN * DDIM);
    float* __restrict__ ob = out + (long)bi * (TOUT * DDIM);

    u64 xi[NP], h[NP], hnew[NP];
    float c[DDIM];
#pragma unroll
    for (int p = 0; p < NP; p++) { xi[p] = 0ull; h[p] = 0ull; }
#pragma unroll
    for (int j = 0; j < DDIM; j++) c[j] = 0.0f;

#pragma unroll 1
    for (int t = 0; t < TLEN; t++) {
        if (t < SLBC) {
            const float* __restrict__ px = xb + t * DDIM;
#pragma unroll
            for (int p = 0; p < 8; p++) xi[p] = pack2(px[2 * p], px[2 * p + 1]);
            xi[8] = pack2(px[16], 0.0f);
        }

        // ---- LSTM cell: hidden units processed in pairs (8 accumulator chains) ----
#pragma unroll
        for (int jj = 0; jj < 8; jj++) {
            const int j0 = 2 * jj, j1 = 2 * jj + 1;
            ulonglong2 b00 = sB[2 * j0], b01 = sB[2 * j0 + 1];
            ulonglong2 b10 = sB[2 * j1], b11 = sB[2 * j1 + 1];
            u64 ai0 = b00.x, af0 = b00.y, ag0 = b01.x, ao0 = b01.y;
            u64 ai1 = b10.x, af1 = b10.y, ag1 = b11.x, ao1 = b11.y;
#pragma unroll
            for (int p = 0; p < NP; p++) {
                ulonglong2 w00 = sWq[(j0 * NP + p) * 4 + 0];
                ulonglong2 w01 = sWq[(j0 * NP + p) * 4 + 1];
                ulonglong2 w02 = sWq[(j0 * NP + p) * 4 + 2];
                ulonglong2 w03 = sWq[(j0 * NP + p) * 4 + 3];
                ulonglong2 w10 = sWq[(j1 * NP + p) * 4 + 0];
                ulonglong2 w11 = sWq[(j1 * NP + p) * 4 + 1];
                ulonglong2 w12 = sWq[(j1 * NP + p) * 4 + 2];
                ulonglong2 w13 = sWq[(j1 * NP + p) * 4 + 3];
                u64 xp = xi[p], hp = h[p];
                fma2a(ai0, xp, w00.x); fma2a(af0, xp, w00.y);
                fma2a(ag0, xp, w01.x); fma2a(ao0, xp, w01.y);
                fma2a(ai1, xp, w10.x); fma2a(af1, xp, w10.y);
                fma2a(ag1, xp, w11.x); fma2a(ao1, xp, w11.y);
                fma2a(ai0, hp, w02.x); fma2a(af0, hp, w02.y);
                fma2a(ag0, hp, w03.x); fma2a(ao0, hp, w03.y);
                fma2a(ai1, hp, w12.x); fma2a(af1, hp, w12.y);
                fma2a(ag1, hp, w13.x); fma2a(ao1, hp, w13.y);
            }
            float hn0, hn1;
            {
                float gi = hadd2(ai0), gf = hadd2(af0), gg = hadd2(ag0), go = hadd2(ao0);
                float si = sigm(gi), sf = sigm(gf), tg = tanhx(gg), so = sigm(go);
                float cn = fmaf(sf, c[j0], si * tg);
                c[j0] = cn;
                hn0 = so * tanhx(cn);
            }
            {
                float gi = hadd2(ai1), gf = hadd2(af1), gg = hadd2(ag1), go = hadd2(ao1);
                float si = sigm(gi), sf = sigm(gf), tg = tanhx(gg), so = sigm(go);
                float cn = fmaf(sf, c[j1], si * tg);
                c[j1] = cn;
                hn1 = so * tanhx(cn);
            }
            hnew[jj] = pack2(hn0, hn1);
        }
        {   // tail j = 16
            const int j = 16;
            ulonglong2 b0 = sB[2 * j], b1 = sB[2 * j + 1];
            u64 ai = b0.x, af = b0.y, ag = b1.x, ao = b1.y;
#pragma unroll
            for (int p = 0; p < NP; p++) {
                ulonglong2 w0 = sWq[(j * NP + p) * 4 + 0];
                ulonglong2 w1 = sWq[(j * NP + p) * 4 + 1];
                ulonglong2 w2 = sWq[(j * NP + p) * 4 + 2];
                ulonglong2 w3 = sWq[(j * NP + p) * 4 + 3];
                u64 xp = xi[p], hp = h[p];
                fma2a(ai, xp, w0.x); fma2a(af, xp, w0.y);
                fma2a(ag, xp, w1.x); fma2a(ao, xp, w1.y);
                fma2a(ai, hp, w2.x); fma2a(af, hp, w2.y);
                fma2a(ag, hp, w3.x); fma2a(ao, hp, w3.y);
            }
            float gi = hadd2(ai), gf = hadd2(af), gg = hadd2(ag), go = hadd2(ao);
            float si = sigm(gi), sf = sigm(gf), tg = tanhx(gg), so = sigm(go);
            float cn = fmaf(sf, c[j], si * tg);
            c[j] = cn;
            hnew[8] = pack2(so * tanhx(cn), 0.0f);
        }
#pragma unroll
        for (int p = 0; p < NP; p++) h[p] = hnew[p];

        if (t >= SLBC - 1) {
            float o[2 * NP];
#pragma unroll
            for (int ccp = 0; ccp < NP; ccp++) {
                u64 a0 = sBlin[2 * ccp], a1 = sBlin[2 * ccp + 1];
#pragma unroll
                for (int p = 0; p < NP; p++) {
                    ulonglong2 w = sLin2[ccp * NP + p];
                    fma2a(a0, h[p], w.x);
                    fma2a(a1, h[p], w.y);
                }
                o[2 * ccp] = hadd2(a0); o[2 * ccp + 1] = hadd2(a1);
            }
            if (t >= SLBC) {
                int tp = t - SLBC;
#pragma unroll
                for (int cc = 0; cc < DDIM; cc++) ob[tp * DDIM + cc] = o[cc];
            }
            // Feedback input for next step.
#pragma unroll
            for (int p = 0; p < 8; p++) xi[p] = pack2(o[2 * p], o[2 * p + 1]);
            xi[8] = pack2(o[16], 0.0f);
        }
    }
}

extern "C" void kernel_launch(void* const* d_in, const int* in_sizes, int n_in,
                              void* d_out, int out_size) {
    const float* x    = (const float*)d_in[0];
    const float* Wih  = (const float*)d_in[1];
    const float* Whh  = (const float*)d_in[2];
    const float* bih  = (const float*)d_in[3];
    const float* bhh  = (const float*)d_in[4];
    const float* Wlin = (const float*)d_in[5];
    const float* blin = (const float*)d_in[6];
    const float* mih  = (const float*)d_in[7];
    const float* mhh  = (const float*)d_in[8];
    float* out = (float*)d_out;

    dim3 grid(BSZ / TPB);   // 1024 CTAs of 64 threads -> 2048 warps
    dim3 block(TPB);
    lstm_kernel<<<grid, block>>>(x, Wih, Whh, bih, bhh, Wlin, blin, mih, mhh, out);
}

// round 9
// speedup vs baseline: 1.3107x; 1.1202x over previous
#include <cuda_runtime.h>

// LSTM_584115552367: B=65536 independent LSTMs, D=H=17, T=50, SLB=30.
// R6 (resubmit after infra failure): R5 compute core + SMEM staging to replace
// scattered LDG/STG (32 lines per instr, ~544 wf/warp-step) with coalesced
// gmem access + conflict-free LDS.

#define BSZ   65536
#define TLEN  50
#define DDIM  17
#define SLBC  30
#define NP    9            // padded d-pairs (18/2)
#define TPB   64
#define TOUT  (TLEN - SLBC)
#define XROW  18           // staging row stride (floats), 8B-aligned rows

typedef unsigned long long u64;

__device__ __forceinline__ u64 pack2(float lo, float hi) {
    u64 r; asm("mov.b64 %0, {%1, %2};" : "=l"(r) : "f"(lo), "f"(hi)); return r;
}
__device__ __forceinline__ void unpack2(u64 v, float &lo, float &hi) {
    asm("mov.b64 {%0, %1}, %2;" : "=f"(lo), "=f"(hi) : "l"(v));
}
__device__ __forceinline__ void fma2a(u64 &acc, u64 a, u64 b) {
    asm("fma.rn.f32x2 %0, %1, %2, %0;" : "+l"(acc) : "l"(a), "l"(b));
}
__device__ __forceinline__ float hadd2(u64 v) {
    float a, b; unpack2(v, a, b); return a + b;
}

__device__ __forceinline__ float ex2f(float x) {
    float r; asm("ex2.approx.f32 %0, %1;" : "=f"(r) : "f"(x)); return r;
}
__device__ __forceinline__ float rcpf(float x) {
    float r; asm("rcp.approx.f32 %0, %1;" : "=f"(r) : "f"(x)); return r;
}
// sigmoid(x) = 1 / (1 + 2^(-x*log2e)); safe at both extremes (rcp(inf)=0).
__device__ __forceinline__ float sigm(float x) {
    return rcpf(1.0f + ex2f(-1.4426950408889634f * x));
}
// tanh(x) = sign(x)*(1-e)/(1+e), e = 2^(-2|x|*log2e); e<=1, no inf/NaN.
__device__ __forceinline__ float tanhx(float x) {
    float ax = fabsf(x);
    float e  = ex2f(-2.8853900817779268f * ax);
    float r  = (1.0f - e) * rcpf(1.0f + e);
    return copysignf(r, x);
}

__global__ void __launch_bounds__(TPB, 7) lstm_kernel(
    const float* __restrict__ x,     // [B, T, D]
    const float* __restrict__ Wih,   // [4D, D]
    const float* __restrict__ Whh,   // [4D, D]
    const float* __restrict__ bih,   // [4D]
    const float* __restrict__ bhh,   // [4D]
    const float* __restrict__ Wlin,  // [D, D]
    const float* __restrict__ blin,  // [D]
    const float* __restrict__ mih,   // [4D, D]
    const float* __restrict__ mhh,   // [4D, D]
    float* __restrict__ out)         // [B, TOUT, D]
{
    __shared__ ulonglong2 sWq[DDIM * NP * 4];
    __shared__ ulonglong2 sB[DDIM * 2];
    __shared__ ulonglong2 sLin2[NP * NP];
    __shared__ u64 sBlin[2 * NP];
    __shared__ float sStage[TPB * XROW];   // x / out staging, one 18-float row per thread

    for (int idx = threadIdx.x; idx < DDIM * NP * 4; idx += TPB) {
        int j = idx / 36, r = idx % 36, p = r / 4, q = r % 4;
        const float* W = (q < 2) ? Wih : Whh;
        const float* M = (q < 2) ? mih : mhh;
        int gA = (q & 1) ? (34 + j) : j;
        int gB = (q & 1) ? (51 + j) : (17 + j);
        int d0 = 2 * p, d1 = 2 * p + 1;
        float a0 = W[gA * DDIM + d0] * M[gA * DDIM + d0];
        float a1 = (d1 < DDIM) ? W[gA * DDIM + d1] * M[gA * DDIM + d1] : 0.0f;
        float b0 = W[gB * DDIM + d0] * M[gB * DDIM + d0];
        float b1 = (d1 < DDIM) ? W[gB * DDIM + d1] * M[gB * DDIM + d1] : 0.0f;
        ulonglong2 v; v.x = pack2(a0, a1); v.y = pack2(b0, b1);
        sWq[idx] = v;
    }
    for (int idx = threadIdx.x; idx < NP * NP; idx += TPB) {
        int ccp = idx / NP, p = idx % NP;
        int c0 = 2 * ccp, c1 = 2 * ccp + 1;
        int d0 = 2 * p, d1 = 2 * p + 1;
        float x0 = Wlin[c0 * DDIM + d0];
        float x1 = (d1 < DDIM) ? Wlin[c0 * DDIM + d1] : 0.0f;
        float y0 = (c1 < DDIM) ? Wlin[c1 * DDIM + d0] : 0.0f;
        float y1 = (c1 < DDIM && d1 < DDIM) ? Wlin[c1 * DDIM + d1] : 0.0f;
        ulonglong2 v; v.x = pack2(x0, x1); v.y = pack2(y0, y1);
        sLin2[idx] = v;
    }
    if (threadIdx.x < DDIM) {
        int j = threadIdx.x;
        ulonglong2 v0, v1;
        v0.x = pack2(bih[j]      + bhh[j],      0.0f);
        v0.y = pack2(bih[17 + j] + bhh[17 + j], 0.0f);
        v1.x = pack2(bih[34 + j] + bhh[34 + j], 0.0f);
        v1.y = pack2(bih[51 + j] + bhh[51 + j], 0.0f);
        sB[2 * j] = v0; sB[2 * j + 1] = v1;
    }
    if (threadIdx.x < 2 * NP) {
        int cc = threadIdx.x;
        sBlin[cc] = (cc < DDIM) ? pack2(blin[cc], 0.0f) : 0ull;
    }
    __syncthreads();

    const int tid = threadIdx.x;
    // CTA's first element; this thread owns element bi0 + tid.
    const long bi0 = (long)blockIdx.x * TPB;
    const float* __restrict__ xg = x + bi0 * (TLEN * DDIM);      // CTA x base
    float* __restrict__ og = out + bi0 * (TOUT * DDIM);          // CTA out base
    const u64* __restrict__ sMyRow = (const u64*)(sStage + tid * XROW);

    u64 xi[NP], h[NP], hnew[NP];
    float c[DDIM];
#pragma unroll
    for (int p = 0; p < NP; p++) { xi[p] = 0ull; h[p] = 0ull; }
#pragma unroll
    for (int j = 0; j < DDIM; j++) c[j] = 0.0f;

#pragma unroll 1
    for (int t = 0; t < TLEN; t++) {
        if (t < SLBC) {
            __syncthreads();   // staging buffer free (prior readers done)
            // Coalesced cooperative load: 64*17 floats for this CTA at step t.
#pragma unroll
            for (int k = 0; k < DDIM; k++) {
                int idx = tid + k * TPB;             // 0..1087, warp-consecutive
                int el = idx / DDIM, d = idx % DDIM;
                sStage[el * XROW + d] = xg[(long)el * (TLEN * DDIM) + t * DDIM + d];
            }
            __syncthreads();
#pragma unroll
            for (int p = 0; p < 8; p++) xi[p] = sMyRow[p];       // LDS.64, 8B-aligned
            {
                float lo, hi; unpack2(sMyRow[8], lo, hi);
                xi[8] = pack2(lo, 0.0f);                          // d=17 slot is junk -> zero
            }
        }

        // ---- LSTM cell: hidden units in pairs (8 accumulator chains) ----
#pragma unroll
        for (int jj = 0; jj < 8; jj++) {
            const int j0 = 2 * jj, j1 = 2 * jj + 1;
            ulonglong2 b00 = sB[2 * j0], b01 = sB[2 * j0 + 1];
            ulonglong2 b10 = sB[2 * j1], b11 = sB[2 * j1 + 1];
            u64 ai0 = b00.x, af0 = b00.y, ag0 = b01.x, ao0 = b01.y;
            u64 ai1 = b10.x, af1 = b10.y, ag1 = b11.x, ao1 = b11.y;
#pragma unroll
            for (int p = 0; p < NP; p++) {
                ulonglong2 w00 = sWq[(j0 * NP + p) * 4 + 0];
                ulonglong2 w01 = sWq[(j0 * NP + p) * 4 + 1];
                ulonglong2 w02 = sWq[(j0 * NP + p) * 4 + 2];
                ulonglong2 w03 = sWq[(j0 * NP + p) * 4 + 3];
                ulonglong2 w10 = sWq[(j1 * NP + p) * 4 + 0];
                ulonglong2 w11 = sWq[(j1 * NP + p) * 4 + 1];
                ulonglong2 w12 = sWq[(j1 * NP + p) * 4 + 2];
                ulonglong2 w13 = sWq[(j1 * NP + p) * 4 + 3];
                u64 xp = xi[p], hp = h[p];
                fma2a(ai0, xp, w00.x); fma2a(af0, xp, w00.y);
                fma2a(ag0, xp, w01.x); fma2a(ao0, xp, w01.y);
                fma2a(ai1, xp, w10.x); fma2a(af1, xp, w10.y);
                fma2a(ag1, xp, w11.x); fma2a(ao1, xp, w11.y);
                fma2a(ai0, hp, w02.x); fma2a(af0, hp, w02.y);
                fma2a(ag0, hp, w03.x); fma2a(ao0, hp, w03.y);
                fma2a(ai1, hp, w12.x); fma2a(af1, hp, w12.y);
                fma2a(ag1, hp, w13.x); fma2a(ao1, hp, w13.y);
            }
            float hn0, hn1;
            {
                float gi = hadd2(ai0), gf = hadd2(af0), gg = hadd2(ag0), go = hadd2(ao0);
                float si = sigm(gi), sf = sigm(gf), tg = tanhx(gg), so = sigm(go);
                float cn = fmaf(sf, c[j0], si * tg);
                c[j0] = cn;
                hn0 = so * tanhx(cn);
            }
            {
                float gi = hadd2(ai1), gf = hadd2(af1), gg = hadd2(ag1), go = hadd2(ao1);
                float si = sigm(gi), sf = sigm(gf), tg = tanhx(gg), so = sigm(go);
                float cn = fmaf(sf, c[j1], si * tg);
                c[j1] = cn;
                hn1 = so * tanhx(cn);
            }
            hnew[jj] = pack2(hn0, hn1);
        }
        {   // tail j = 16
            const int j = 16;
            ulonglong2 b0 = sB[2 * j], b1 = sB[2 * j + 1];
            u64 ai = b0.x, af = b0.y, ag = b1.x, ao = b1.y;
#pragma unroll
            for (int p = 0; p < NP; p++) {
                ulonglong2 w0 = sWq[(j * NP + p) * 4 + 0];
                ulonglong2 w1 = sWq[(j * NP + p) * 4 + 1];
                ulonglong2 w2 = sWq[(j * NP + p) * 4 + 2];
                ulonglong2 w3 = sWq[(j * NP + p) * 4 + 3];
                u64 xp = xi[p], hp = h[p];
                fma2a(ai, xp, w0.x); fma2a(af, xp, w0.y);
                fma2a(ag, xp, w1.x); fma2a(ao, xp, w1.y);
                fma2a(ai, hp, w2.x); fma2a(af, hp, w2.y);
                fma2a(ag, hp, w3.x); fma2a(ao, hp, w3.y);
            }
            float gi = hadd2(ai), gf = hadd2(af), gg = hadd2(ag), go = hadd2(ao);
            float si = sigm(gi), sf = sigm(gf), tg = tanhx(gg), so = sigm(go);
            float cn = fmaf(sf, c[j], si * tg);
            c[j] = cn;
            hnew[8] = pack2(so * tanhx(cn), 0.0f);
        }
#pragma unroll
        for (int p = 0; p < NP; p++) h[p] = hnew[p];

        if (t >= SLBC - 1) {
            float o[2 * NP];
#pragma unroll
            for (int ccp = 0; ccp < NP; ccp++) {
                u64 a0 = sBlin[2 * ccp], a1 = sBlin[2 * ccp + 1];
#pragma unroll
                for (int p = 0; p < NP; p++) {
                    ulonglong2 w = sLin2[ccp * NP + p];
                    fma2a(a0, h[p], w.x);
                    fma2a(a1, h[p], w.y);
                }
                o[2 * ccp] = hadd2(a0); o[2 * ccp + 1] = hadd2(a1);
            }
            if (t >= SLBC) {
                int tp = t - SLBC;
                __syncthreads();   // buffer free (prior step's STG readers done)
                u64* myRowW = (u64*)(sStage + tid * XROW);
#pragma unroll
                for (int p = 0; p < NP; p++)
                    myRowW[p] = pack2(o[2 * p], (2 * p + 1 < DDIM) ? o[2 * p + 1] : 0.0f);
                __syncthreads();
                // Coalesced cooperative store of this step's 64*17 outputs.
#pragma unroll
                for (int k = 0; k < DDIM; k++) {
                    int idx = tid + k * TPB;
                    int el = idx / DDIM, d = idx % DDIM;
                    og[(long)el * (TOUT * DDIM) + tp * DDIM + d] = sStage[el * XROW + d];
                }
            }
            // Feedback input for next step.
#pragma unroll
            for (int p = 0; p < 8; p++) xi[p] = pack2(o[2 * p], o[2 * p + 1]);
            xi[8] = pack2(o[16], 0.0f);
        }
    }
}

extern "C" void kernel_launch(void* const* d_in, const int* in_sizes, int n_in,
                              void* d_out, int out_size) {
    const float* x    = (const float*)d_in[0];
    const float* Wih  = (const float*)d_in[1];
    const float* Whh  = (const float*)d_in[2];
    const float* bih  = (const float*)d_in[3];
    const float* bhh  = (const float*)d_in[4];
    const float* Wlin = (const float*)d_in[5];
    const float* blin = (const float*)d_in[6];
    const float* mih  = (const float*)d_in[7];
    const float* mhh  = (const float*)d_in[8];
    float* out = (float*)d_out;

    dim3 grid(BSZ / TPB);   // 1024 CTAs of 64 threads -> 2048 warps
    dim3 block(TPB);
    lstm_kernel<<<grid, block>>>(x, Wih, Whh, bih, bhh, Wlin, blin, mih, mhh, out);
}